// round 5
// baseline (speedup 1.0000x reference)
#include <cuda_runtime.h>
#include <cuda_fp16.h>
#include <cstdint>

// N=100000, E=1600000, D=8, K=1, C=32 (dims from in_sizes at runtime).
#define MAXN 100352
#define MAXE 1638400

__device__ __align__(16) __half g_xgh[MAXN * 32];    // x @ g  (fp16 gather payload)
__device__ __align__(16) float g_rootb[MAXN * 32];   // root term (layer 1)
__device__ __align__(16) float g_rootb2[MAXN * 32];  // root term (layer 2)
__device__ __align__(16) float g_h[MAXN * 32];       // layer-1 output (fp32)
__device__ __align__(16) float2 g_eg1[MAXE];         // (src, gau1) sorted by dst
__device__ __align__(16) float2 g_eg2[MAXE];         // (src, gau2) sorted by dst
__device__ int g_cnt[MAXN];                           // in-degree histogram
__device__ int g_rowptr[MAXN + 1];                    // CSR row pointers (by dst)
__device__ int g_cursor[MAXN];                        // scatter cursors

// ---------------- CSR build ----------------

__global__ void __launch_bounds__(256) hist_k(const int* __restrict__ ei, int* __restrict__ cnt, int E) {
    int e = blockIdx.x * blockDim.x + threadIdx.x;
    if (e < E) atomicAdd(cnt + __ldg(ei + E + e), 1);
}

// Single-block exclusive scan over N counts -> rowptr + cursor in one launch.
__global__ void __launch_bounds__(1024) scan_k(const int* __restrict__ cnt,
                                               int* __restrict__ rowptr,
                                               int* __restrict__ cursor,
                                               int N, int E) {
    __shared__ int sh[1024];
    int t = threadIdx.x;
    int len = (N + 1023) >> 10;
    int beg = t * len;
    int end = min(beg + len, N);

    int sum = 0;
    for (int i = beg; i < end; i++) sum += __ldg(cnt + i);
    sh[t] = sum;
    __syncthreads();
    for (int off = 1; off < 1024; off <<= 1) {
        int add = (t >= off) ? sh[t - off] : 0;
        __syncthreads();
        sh[t] += add;
        __syncthreads();
    }
    int run = sh[t] - sum;  // exclusive prefix for this thread's chunk
    for (int i = beg; i < end; i++) {
        int c = __ldg(cnt + i);
        rowptr[i] = run;
        cursor[i] = run;
        run += c;
    }
    if (t == 1023) rowptr[N] = E;
}

// Gaussian weights for both layers + scatter (src, gau) records to the
// dst-sorted slot. Two 8B writes per edge.
__global__ void __launch_bounds__(256) gau_scatter_k(
    const int* __restrict__ ei,
    const float4* __restrict__ ea,    // [E,8] viewed as [E,2] float4
    const float* __restrict__ mu1, const float* __restrict__ s1,
    const float* __restrict__ mu2, const float* __restrict__ s2,
    int* __restrict__ cursor,
    float2* __restrict__ eg1, float2* __restrict__ eg2, int E) {
    int e = blockIdx.x * blockDim.x + threadIdx.x;
    if (e >= E) return;
    float4 a = ea[e * 2];
    float4 b = ea[e * 2 + 1];
    float v[8] = {a.x, a.y, a.z, a.w, b.x, b.y, b.z, b.w};
    float t1 = 0.f, t2 = 0.f;
#pragma unroll
    for (int d = 0; d < 8; d++) {
        float d1 = v[d] - __ldg(mu1 + d);
        float d2 = v[d] - __ldg(mu2 + d);
        t1 += (-0.5f * d1 * d1) / (1e-15f + __ldg(s1 + d) * __ldg(s1 + d));
        t2 += (-0.5f * d2 * d2) / (1e-15f + __ldg(s2 + d) * __ldg(s2 + d));
    }
    int src = __ldg(ei + e);
    int dst = __ldg(ei + E + e);
    int pos = atomicAdd(cursor + dst, 1);
    float sf = __int_as_float(src);
    eg1[pos] = make_float2(sf, __expf(t1));
    eg2[pos] = make_float2(sf, __expf(t2));
}

// ---------------- GEMM (register weights, fp16 xg output) ----------------

__global__ void __launch_bounds__(256) gemm_k(
    const float* __restrict__ xin,
    const float* __restrict__ g,
    const float* __restrict__ root,
    const float* __restrict__ bias,
    __half* __restrict__ xg,
    float* __restrict__ rb_out,
    int N) {
    __shared__ float sx[128][32];
    const int t = threadIdx.x;
    const int lane = t & 31;
    const int w = t >> 5;

    float wg[32], wr[32];
#pragma unroll
    for (int k = 0; k < 32; k++) {
        wg[k] = __ldg(g + k * 32 + lane);
        wr[k] = __ldg(root + k * 32 + lane);
    }
    const float bv = __ldg(bias + lane);

    const int base = blockIdx.x * 128;
    const int nrows = min(128, N - base);

    for (int i = t; i < nrows * 32; i += 256)
        sx[i >> 5][i & 31] = xin[(size_t)base * 32 + i];
    __syncthreads();

    for (int r = w; r < nrows; r += 8) {
        float a = 0.0f, b = bv;
#pragma unroll
        for (int k = 0; k < 32; k++) {
            float xv = sx[r][k];
            a = fmaf(xv, wg[k], a);
            b = fmaf(xv, wr[k], b);
        }
        size_t o = (size_t)(base + r) * 32 + lane;
        xg[o] = __float2half_rn(a);
        rb_out[o] = b;
    }
}

// ---------------- Pull aggregation (atomic-free) ----------------
// One warp per dst node; lane = channel. Per edge: one 8B broadcast record +
// one coalesced 64B fp16 row. fp32 accumulate; mean + root in epilogue.
__global__ void __launch_bounds__(256) pull_k(
    const int* __restrict__ rowptr,
    const float2* __restrict__ eg,
    const __half* __restrict__ xg,    // [N,32] fp16
    const float* __restrict__ rootb,  // [N,32]
    float* __restrict__ out,          // [N,32]
    int N) {
    int warp = (blockIdx.x * blockDim.x + threadIdx.x) >> 5;
    int lane = threadIdx.x & 31;
    if (warp >= N) return;

    int s = __ldg(rowptr + warp);
    int e = __ldg(rowptr + warp + 1);

    float acc0 = 0.f, acc1 = 0.f;
    int j = s;
    for (; j + 4 <= e; j += 4) {
        float2 p0 = __ldg(eg + j);
        float2 p1 = __ldg(eg + j + 1);
        float2 p2 = __ldg(eg + j + 2);
        float2 p3 = __ldg(eg + j + 3);
        float x0 = __half2float(__ldg(xg + (size_t)__float_as_int(p0.x) * 32 + lane));
        float x1 = __half2float(__ldg(xg + (size_t)__float_as_int(p1.x) * 32 + lane));
        float x2 = __half2float(__ldg(xg + (size_t)__float_as_int(p2.x) * 32 + lane));
        float x3 = __half2float(__ldg(xg + (size_t)__float_as_int(p3.x) * 32 + lane));
        acc0 = fmaf(p0.y, x0, acc0);
        acc1 = fmaf(p1.y, x1, acc1);
        acc0 = fmaf(p2.y, x2, acc0);
        acc1 = fmaf(p3.y, x3, acc1);
    }
    for (; j < e; j++) {
        float2 p = __ldg(eg + j);
        float xv = __half2float(__ldg(xg + (size_t)__float_as_int(p.x) * 32 + lane));
        acc0 = fmaf(p.y, xv, acc0);
    }

    int deg = e - s;
    float rinv = (deg > 0) ? (1.0f / (float)deg) : 0.0f;
    size_t o = (size_t)warp * 32 + lane;
    out[o] = (acc0 + acc1) * rinv + rootb[o];
}

extern "C" void kernel_launch(void* const* d_in, const int* in_sizes, int n_in,
                              void* d_out, int out_size) {
    const int*   ei  = (const int*)d_in[0];
    const float* ew  = (const float*)d_in[1];
    const float* x   = (const float*)d_in[2];
    const float* g1  = (const float*)d_in[3];
    const float* mu1 = (const float*)d_in[4];
    const float* s1  = (const float*)d_in[5];
    const float* r1  = (const float*)d_in[6];
    const float* b1  = (const float*)d_in[7];
    const float* g2  = (const float*)d_in[8];
    const float* mu2 = (const float*)d_in[9];
    const float* s2  = (const float*)d_in[10];
    const float* r2  = (const float*)d_in[11];
    const float* b2  = (const float*)d_in[12];

    const int E = in_sizes[0] / 2;
    const int N = in_sizes[2] / 32;

    __half* xgh;
    float *rootb, *rootb2, *h;
    float2 *eg1, *eg2;
    int *cnt, *rowptr, *cursor;
    cudaGetSymbolAddress((void**)&xgh, g_xgh);
    cudaGetSymbolAddress((void**)&rootb, g_rootb);
    cudaGetSymbolAddress((void**)&rootb2, g_rootb2);
    cudaGetSymbolAddress((void**)&h, g_h);
    cudaGetSymbolAddress((void**)&eg1, g_eg1);
    cudaGetSymbolAddress((void**)&eg2, g_eg2);
    cudaGetSymbolAddress((void**)&cnt, g_cnt);
    cudaGetSymbolAddress((void**)&rowptr, g_rowptr);
    cudaGetSymbolAddress((void**)&cursor, g_cursor);

    const int eb = (E + 255) / 256;
    const int gemm_blocks = (N + 127) / 128;
    const int pull_blocks = (N + 7) / 8;

    // ---- CSR build (shared by both layers) ----
    cudaMemsetAsync(cnt, 0, (size_t)N * sizeof(int), 0);
    hist_k<<<eb, 256>>>(ei, cnt, E);
    scan_k<<<1, 1024>>>(cnt, rowptr, cursor, N, E);
    gau_scatter_k<<<eb, 256>>>(ei, (const float4*)ew, mu1, s1, mu2, s2, cursor, eg1, eg2, E);

    // ---- layer 1 ----
    gemm_k<<<gemm_blocks, 256>>>(x, g1, r1, b1, xgh, rootb, N);
    pull_k<<<pull_blocks, 256>>>(rowptr, eg1, xgh, rootb, h, N);

    // ---- layer 2 ----
    gemm_k<<<gemm_blocks, 256>>>(h, g2, r2, b2, xgh, rootb2, N);
    pull_k<<<pull_blocks, 256>>>(rowptr, eg2, xgh, rootb2, (float*)d_out, N);
}

// round 6
// speedup vs baseline: 1.7807x; 1.7807x over previous
#include <cuda_runtime.h>
#include <cstdint>

// N=100000, E=1600000, D=8, K=1, C=32 (dims from in_sizes at runtime).
#define MAXN 100352
#define MAXE 1638400
#define SCAN_BLK 1024
#define MAX_SB 128   // max scan blocks (ceil(MAXN/1024) = 98)

__device__ __align__(16) float g_xg[MAXN * 32];      // x @ g
__device__ __align__(16) float g_rootb[MAXN * 32];   // root term (layer 1)
__device__ __align__(16) float g_rootb2[MAXN * 32];  // root term (layer 2)
__device__ __align__(16) float g_h[MAXN * 32];       // layer-1 output
__device__ __align__(16) float4 g_edges[MAXE];       // packed (src, gau1, gau2, -) sorted by dst
__device__ int g_cnt[MAXN];                           // in-degree histogram
__device__ int g_rowptr[MAXN + 1];                    // CSR row pointers (by dst)
__device__ int g_cursor[MAXN];                        // scatter cursors
__device__ int g_bsum[MAX_SB];                        // scan block sums

// ---------------- CSR build ----------------

__global__ void __launch_bounds__(256) hist_k(const int* __restrict__ ei, int* __restrict__ cnt, int E) {
    int e = blockIdx.x * blockDim.x + threadIdx.x;
    if (e < E) atomicAdd(cnt + __ldg(ei + E + e), 1);
}

// Per-block exclusive scan of 1024 counts; block totals to bsum.
__global__ void __launch_bounds__(SCAN_BLK) scan1_k(const int* __restrict__ cnt,
                                                    int* __restrict__ rowptr,
                                                    int* __restrict__ bsum, int N) {
    __shared__ int sh[SCAN_BLK];
    int t = threadIdx.x;
    int i = blockIdx.x * SCAN_BLK + t;
    int v = (i < N) ? cnt[i] : 0;
    sh[t] = v;
    __syncthreads();
    for (int off = 1; off < SCAN_BLK; off <<= 1) {
        int add = (t >= off) ? sh[t - off] : 0;
        __syncthreads();
        sh[t] += add;
        __syncthreads();
    }
    if (i < N) rowptr[i] = sh[t] - v;  // exclusive
    if (t == SCAN_BLK - 1) bsum[blockIdx.x] = sh[t];
}

// Exclusive scan of block sums (single block).
__global__ void __launch_bounds__(MAX_SB) scan2_k(int* __restrict__ bsum, int nb) {
    __shared__ int sh[MAX_SB];
    int t = threadIdx.x;
    int v = (t < nb) ? bsum[t] : 0;
    sh[t] = v;
    __syncthreads();
    for (int off = 1; off < MAX_SB; off <<= 1) {
        int add = (t >= off) ? sh[t - off] : 0;
        __syncthreads();
        sh[t] += add;
        __syncthreads();
    }
    if (t < nb) bsum[t] = sh[t] - v;
}

// Add block offsets; init cursors; set rowptr[N]=E.
__global__ void __launch_bounds__(SCAN_BLK) scan3_k(int* __restrict__ rowptr,
                                                    int* __restrict__ cursor,
                                                    const int* __restrict__ bsum,
                                                    int N, int E) {
    int i = blockIdx.x * SCAN_BLK + threadIdx.x;
    if (i < N) {
        int v = rowptr[i] + bsum[blockIdx.x];
        rowptr[i] = v;
        cursor[i] = v;
    }
    if (i == 0) rowptr[N] = E;
}

// Compute both layers' gaussian weights and scatter packed edge records
// (src, gau1, gau2) to their dst-sorted slot. One 16B write per edge.
__global__ void __launch_bounds__(256) gau_scatter_k(
    const int* __restrict__ ei,
    const float4* __restrict__ ea,    // [E,8] viewed as [E,2] float4
    const float* __restrict__ mu1, const float* __restrict__ s1,
    const float* __restrict__ mu2, const float* __restrict__ s2,
    int* __restrict__ cursor,
    float4* __restrict__ edges, int E) {
    int e = blockIdx.x * blockDim.x + threadIdx.x;
    if (e >= E) return;
    float4 a = ea[e * 2];
    float4 b = ea[e * 2 + 1];
    float v[8] = {a.x, a.y, a.z, a.w, b.x, b.y, b.z, b.w};
    float t1 = 0.f, t2 = 0.f;
#pragma unroll
    for (int d = 0; d < 8; d++) {
        float d1 = v[d] - __ldg(mu1 + d);
        float d2 = v[d] - __ldg(mu2 + d);
        t1 += (-0.5f * d1 * d1) / (1e-15f + __ldg(s1 + d) * __ldg(s1 + d));
        t2 += (-0.5f * d2 * d2) / (1e-15f + __ldg(s2 + d) * __ldg(s2 + d));
    }
    int src = __ldg(ei + e);
    int dst = __ldg(ei + E + e);
    int pos = atomicAdd(cursor + dst, 1);
    float4 rec;
    rec.x = __int_as_float(src);
    rec.y = __expf(t1);
    rec.z = __expf(t2);
    rec.w = 0.f;
    edges[pos] = rec;
}

// ---------------- GEMM (register weights) ----------------

__global__ void __launch_bounds__(256) gemm_k(
    const float* __restrict__ xin,
    const float* __restrict__ g,
    const float* __restrict__ root,
    const float* __restrict__ bias,
    float* __restrict__ xg,
    float* __restrict__ rb_out,
    int N) {
    __shared__ float sx[128][32];
    const int t = threadIdx.x;
    const int lane = t & 31;
    const int w = t >> 5;

    float wg[32], wr[32];
#pragma unroll
    for (int k = 0; k < 32; k++) {
        wg[k] = __ldg(g + k * 32 + lane);
        wr[k] = __ldg(root + k * 32 + lane);
    }
    const float bv = __ldg(bias + lane);

    const int base = blockIdx.x * 128;
    const int nrows = min(128, N - base);

    for (int i = t; i < nrows * 32; i += 256)
        sx[i >> 5][i & 31] = xin[(size_t)base * 32 + i];
    __syncthreads();

    for (int r = w; r < nrows; r += 8) {
        float a = 0.0f, b = bv;
#pragma unroll
        for (int k = 0; k < 32; k++) {
            float xv = sx[r][k];
            a = fmaf(xv, wg[k], a);
            b = fmaf(xv, wr[k], b);
        }
        size_t o = (size_t)(base + r) * 32 + lane;
        xg[o] = a;
        rb_out[o] = b;
    }
}

// ---------------- Pull aggregation (atomic-free, software-pipelined) ----------------
// One warp per dst node; lane = channel. Records for group i+1 are loaded
// before the gathers of group i are consumed, doubling effective MLP.
template <int LAYER>
__global__ void __launch_bounds__(256) pull_k(
    const int* __restrict__ rowptr,
    const float4* __restrict__ edges,
    const float* __restrict__ xg,     // [N,32]
    const float* __restrict__ rootb,  // [N,32]
    float* __restrict__ out,          // [N,32]
    int N) {
    int warp = (blockIdx.x * blockDim.x + threadIdx.x) >> 5;
    int lane = threadIdx.x & 31;
    if (warp >= N) return;

    int s = __ldg(rowptr + warp);
    int e = __ldg(rowptr + warp + 1);
    int deg = e - s;
    int nfull = deg >> 2;

    float acc0 = 0.f, acc1 = 0.f;

    if (nfull > 0) {
        float4 r0 = edges[s], r1 = edges[s + 1], r2 = edges[s + 2], r3 = edges[s + 3];
        for (int grp = 1; grp < nfull; grp++) {
            int jn = s + grp * 4;
            float4 n0 = edges[jn], n1 = edges[jn + 1], n2 = edges[jn + 2], n3 = edges[jn + 3];
            float x0 = xg[(size_t)__float_as_int(r0.x) * 32 + lane];
            float x1 = xg[(size_t)__float_as_int(r1.x) * 32 + lane];
            float x2 = xg[(size_t)__float_as_int(r2.x) * 32 + lane];
            float x3 = xg[(size_t)__float_as_int(r3.x) * 32 + lane];
            acc0 = fmaf((LAYER == 1) ? r0.y : r0.z, x0, acc0);
            acc1 = fmaf((LAYER == 1) ? r1.y : r1.z, x1, acc1);
            acc0 = fmaf((LAYER == 1) ? r2.y : r2.z, x2, acc0);
            acc1 = fmaf((LAYER == 1) ? r3.y : r3.z, x3, acc1);
            r0 = n0; r1 = n1; r2 = n2; r3 = n3;
        }
        float x0 = xg[(size_t)__float_as_int(r0.x) * 32 + lane];
        float x1 = xg[(size_t)__float_as_int(r1.x) * 32 + lane];
        float x2 = xg[(size_t)__float_as_int(r2.x) * 32 + lane];
        float x3 = xg[(size_t)__float_as_int(r3.x) * 32 + lane];
        acc0 = fmaf((LAYER == 1) ? r0.y : r0.z, x0, acc0);
        acc1 = fmaf((LAYER == 1) ? r1.y : r1.z, x1, acc1);
        acc0 = fmaf((LAYER == 1) ? r2.y : r2.z, x2, acc0);
        acc1 = fmaf((LAYER == 1) ? r3.y : r3.z, x3, acc1);
    }
    for (int j = s + nfull * 4; j < e; j++) {
        float4 p = edges[j];
        float xv = xg[(size_t)__float_as_int(p.x) * 32 + lane];
        acc0 = fmaf((LAYER == 1) ? p.y : p.z, xv, acc0);
    }

    float rinv = (deg > 0) ? (1.0f / (float)deg) : 0.0f;
    size_t o = (size_t)warp * 32 + lane;
    out[o] = (acc0 + acc1) * rinv + rootb[o];
}

extern "C" void kernel_launch(void* const* d_in, const int* in_sizes, int n_in,
                              void* d_out, int out_size) {
    const int*   ei  = (const int*)d_in[0];
    const float* ew  = (const float*)d_in[1];
    const float* x   = (const float*)d_in[2];
    const float* g1  = (const float*)d_in[3];
    const float* mu1 = (const float*)d_in[4];
    const float* s1  = (const float*)d_in[5];
    const float* r1  = (const float*)d_in[6];
    const float* b1  = (const float*)d_in[7];
    const float* g2  = (const float*)d_in[8];
    const float* mu2 = (const float*)d_in[9];
    const float* s2  = (const float*)d_in[10];
    const float* r2  = (const float*)d_in[11];
    const float* b2  = (const float*)d_in[12];

    const int E = in_sizes[0] / 2;
    const int N = in_sizes[2] / 32;

    float *xg, *rootb, *rootb2, *h;
    float4* edges;
    int *cnt, *rowptr, *cursor, *bsum;
    cudaGetSymbolAddress((void**)&xg, g_xg);
    cudaGetSymbolAddress((void**)&rootb, g_rootb);
    cudaGetSymbolAddress((void**)&rootb2, g_rootb2);
    cudaGetSymbolAddress((void**)&h, g_h);
    cudaGetSymbolAddress((void**)&edges, g_edges);
    cudaGetSymbolAddress((void**)&cnt, g_cnt);
    cudaGetSymbolAddress((void**)&rowptr, g_rowptr);
    cudaGetSymbolAddress((void**)&cursor, g_cursor);
    cudaGetSymbolAddress((void**)&bsum, g_bsum);

    const int nb = (N + SCAN_BLK - 1) / SCAN_BLK;
    const int eb = (E + 255) / 256;
    const int gemm_blocks = (N + 127) / 128;
    const int pull_blocks = (N + 7) / 8;

    // ---- CSR build (shared by both layers) ----
    cudaMemsetAsync(cnt, 0, (size_t)N * sizeof(int), 0);
    hist_k<<<eb, 256>>>(ei, cnt, E);
    scan1_k<<<nb, SCAN_BLK>>>(cnt, rowptr, bsum, N);
    scan2_k<<<1, MAX_SB>>>(bsum, nb);
    scan3_k<<<nb, SCAN_BLK>>>(rowptr, cursor, bsum, N, E);
    gau_scatter_k<<<eb, 256>>>(ei, (const float4*)ew, mu1, s1, mu2, s2, cursor, edges, E);

    // ---- layer 1 ----
    gemm_k<<<gemm_blocks, 256>>>(x, g1, r1, b1, xg, rootb, N);
    pull_k<1><<<pull_blocks, 256>>>(rowptr, edges, xg, rootb, h, N);

    // ---- layer 2 ----
    gemm_k<<<gemm_blocks, 256>>>(h, g2, r2, b2, xg, rootb2, N);
    pull_k<2><<<pull_blocks, 256>>>(rowptr, edges, xg, rootb2, (float*)d_out, N);
}